// round 8
// baseline (speedup 1.0000x reference)
#include <cuda_runtime.h>
#include <cstdint>

#define BATCH 64
#define NSEQ  2048
#define CDIM  128
#define HP    64
#define WP    32
#define HG    32   // HP / POOL
#define D_SCALE 0.08838834764831845f  // 1/sqrt(128)

// Scratch: Q,K,V in [B, C, N] (spatial-major) layout. V plane is overwritten
// with the attention output by attn_kernel (each CTA exclusively owns its plane,
// and proj writes it fully on every graph replay -> deterministic).
__device__ float g_QT[(size_t)BATCH * CDIM * NSEQ];
__device__ float g_KT[(size_t)BATCH * CDIM * NSEQ];
__device__ float g_VT[(size_t)BATCH * CDIM * NSEQ];

// Precomputed W fragments: [p][(nt*8+ks)*32 + lane] -> uint4 (b0hi, b1hi, b0lo, b1lo)
__device__ uint4 g_Wpk[3 * 4096];

#define SSTR 132   // proj smem row stride (floats)

// Pack two fp32 into bf16x2: e0 -> low 16 bits (even k), e1 -> high (odd k).
__device__ __forceinline__ uint32_t bf16x2_of(float e0, float e1) {
    uint32_t r;
    asm("cvt.rn.bf16x2.f32 %0, %1, %2;" : "=r"(r) : "f"(e1), "f"(e0));
    return r;
}
__device__ __forceinline__ float lo_f(uint32_t p) { return __uint_as_float(p << 16); }
__device__ __forceinline__ float hi_f(uint32_t p) { return __uint_as_float(p & 0xffff0000u); }

__device__ __forceinline__ void mma_bf16(float& d0, float& d1, float& d2, float& d3,
                                         uint32_t a0, uint32_t a1, uint32_t a2, uint32_t a3,
                                         uint32_t b0, uint32_t b1) {
    asm volatile(
        "mma.sync.aligned.m16n8k16.row.col.f32.bf16.bf16.f32 "
        "{%0,%1,%2,%3}, {%4,%5,%6,%7}, {%8,%9}, {%0,%1,%2,%3};"
        : "+f"(d0), "+f"(d1), "+f"(d2), "+f"(d3)
        : "r"(a0), "r"(a1), "r"(a2), "r"(a3), "r"(b0), "r"(b1));
}

// ---------------------------------------------------------------------------
// Kernel 0: convert W matrices into MMA-fragment-packed bf16 hi/lo, once.
// ---------------------------------------------------------------------------
__global__ __launch_bounds__(256) void prep_w_kernel(
    const float* __restrict__ Wq, const float* __restrict__ Wk,
    const float* __restrict__ Wv)
{
    const int p = blockIdx.x;
    const float* W = (p == 0) ? Wq : (p == 1) ? Wk : Wv;
    const int t = threadIdx.x;
    #pragma unroll
    for (int i = 0; i < 16; ++i) {
        const int pos  = t + i * 256;        // 0..4095
        const int lane = pos & 31;
        const int ks   = (pos >> 5) & 7;
        const int nt   = pos >> 8;
        const int gj   = lane >> 2;
        const int s    = lane & 3;
        const int j    = nt * 8 + gj;
        const int c0   = ks * 16 + 2 * s;
        const float w0 = W[j * CDIM + c0],     w1 = W[j * CDIM + c0 + 1];
        const float w2 = W[j * CDIM + c0 + 8], w3 = W[j * CDIM + c0 + 9];
        uint32_t x = bf16x2_of(w0, w1);
        uint32_t y = bf16x2_of(w2, w3);
        uint32_t z = bf16x2_of(w0 - lo_f(x), w1 - hi_f(x));
        uint32_t w = bf16x2_of(w2 - lo_f(y), w3 - hi_f(y));
        g_Wpk[p * 4096 + pos] = make_uint4(x, y, z, w);
    }
}

// ---------------------------------------------------------------------------
// Kernel 1: projection GEMMs (proven R7 version).
// ---------------------------------------------------------------------------
__global__ __launch_bounds__(512) void proj_mma_kernel(
    const float* __restrict__ X,
    const float* __restrict__ bq, const float* __restrict__ bk,
    const float* __restrict__ bv)
{
    extern __shared__ float sm[];
    float* Xs  = sm;                        // [m][c] 128 x SSTR fp32 (67.6 KB)
    uint4* Wpk = (uint4*)(sm + 128 * SSTR); // [16 nt][8 ks][32 lane] uint4 (64 KB)

    const int t    = threadIdx.x;
    const int warp = t >> 5;
    const int lane = t & 31;
    const int M0   = blockIdx.x * 128;
    const int bidx = M0 >> 11;
    const int n0   = M0 & 2047;

    {
        const int r  = t >> 5;
        const int c4 = (t & 31) << 2;
        #pragma unroll
        for (int it = 0; it < 8; ++it) {
            const int row = it * 16 + r;
            float4 xv = *(const float4*)(X + (size_t)(M0 + row) * CDIM + c4);
            *(float4*)(Xs + row * SSTR + c4) = xv;
        }
    }

    const int g      = lane >> 2;
    const int tid    = lane & 3;
    const int mgroup = warp & 7;
    const int nhalf  = warp >> 3;
    const int mbase  = mgroup * 16;

    #pragma unroll 1
    for (int p = 0; p < 3; ++p) {
        const float* bias = (p == 0) ? bq : (p == 1) ? bk : bv;
        float* OutT       = (p == 0) ? g_QT : (p == 1) ? g_KT : g_VT;

        __syncthreads();

        #pragma unroll
        for (int i = 0; i < 8; ++i)
            Wpk[t + i * 512] = g_Wpk[p * 4096 + t + i * 512];
        __syncthreads();

        float acc[8][4];
        #pragma unroll
        for (int nt = 0; nt < 8; ++nt)
            #pragma unroll
            for (int q = 0; q < 4; ++q) acc[nt][q] = 0.0f;

        #pragma unroll
        for (int ks = 0; ks < 8; ++ks) {
            const int c0 = ks * 16 + 2 * tid;
            const float* xr0 = Xs + (mbase + g) * SSTR + c0;
            const float* xr1 = Xs + (mbase + g + 8) * SSTR + c0;
            float2 x00 = *(const float2*)(xr0);
            float2 x02 = *(const float2*)(xr0 + 8);
            float2 x10 = *(const float2*)(xr1);
            float2 x12 = *(const float2*)(xr1 + 8);
            uint32_t ah0 = bf16x2_of(x00.x, x00.y);
            uint32_t ah1 = bf16x2_of(x10.x, x10.y);
            uint32_t ah2 = bf16x2_of(x02.x, x02.y);
            uint32_t ah3 = bf16x2_of(x12.x, x12.y);
            uint32_t al0 = bf16x2_of(x00.x - lo_f(ah0), x00.y - hi_f(ah0));
            uint32_t al1 = bf16x2_of(x10.x - lo_f(ah1), x10.y - hi_f(ah1));
            uint32_t al2 = bf16x2_of(x02.x - lo_f(ah2), x02.y - hi_f(ah2));
            uint32_t al3 = bf16x2_of(x12.x - lo_f(ah3), x12.y - hi_f(ah3));

            #pragma unroll
            for (int nt = 0; nt < 8; ++nt) {
                const int ntg = nhalf * 8 + nt;
                uint4 w = Wpk[(ntg * 8 + ks) * 32 + lane];
                mma_bf16(acc[nt][0], acc[nt][1], acc[nt][2], acc[nt][3],
                         ah0, ah1, ah2, ah3, w.x, w.y);
                mma_bf16(acc[nt][0], acc[nt][1], acc[nt][2], acc[nt][3],
                         al0, al1, al2, al3, w.x, w.y);
                mma_bf16(acc[nt][0], acc[nt][1], acc[nt][2], acc[nt][3],
                         ah0, ah1, ah2, ah3, w.z, w.w);
            }
        }

        __syncthreads();

        float* T = (float*)Wpk;
        #pragma unroll
        for (int nt = 0; nt < 8; ++nt) {
            const int j0 = nhalf * 64 + nt * 8 + 2 * tid;
            const float b0v = __ldg(bias + j0);
            const float b1v = __ldg(bias + j0 + 1);
            float v0 = acc[nt][0] + b0v;
            float v1 = acc[nt][1] + b1v;
            float v2 = acc[nt][2] + b0v;
            float v3 = acc[nt][3] + b1v;
            v0 = 1.0f / (1.0f + __expf(-v0));
            v1 = 1.0f / (1.0f + __expf(-v1));
            v2 = 1.0f / (1.0f + __expf(-v2));
            v3 = 1.0f / (1.0f + __expf(-v3));
            T[j0 * SSTR + mbase + g]           = v0;
            T[(j0 + 1) * SSTR + mbase + g]     = v1;
            T[j0 * SSTR + mbase + g + 8]       = v2;
            T[(j0 + 1) * SSTR + mbase + g + 8] = v3;
        }
        __syncthreads();

        #pragma unroll
        for (int it = 0; it < 8; ++it) {
            const int idx = t + it * 512;
            const int j   = idx >> 5;
            const int m4  = (idx & 31) << 2;
            float4 v = *(const float4*)(T + j * SSTR + m4);
            *(float4*)(OutT + ((size_t)bidx * CDIM + j) * NSEQ + n0 + m4) = v;
        }
    }
}

// ---------------------------------------------------------------------------
// Kernel 2: per-(b,c) dual-softmax attention. Registerized: row data preloaded
// into registers, broadcasts done via warp shuffles instead of smem -> 4.6x
// fewer smem crossbar wavefronts than R4. Same data layouts & summation order.
// ---------------------------------------------------------------------------
__global__ __launch_bounds__(256) void attn_kernel()
{
    const int bc = blockIdx.x;                      // b*128 + c
    const float* Qp = g_QT + (size_t)bc * NSEQ;
    const float* Kp = g_KT + (size_t)bc * NSEQ;
    const float* Vp = g_VT + (size_t)bc * NSEQ;
    float* Op = g_VT + (size_t)bc * NSEQ;           // overwrite V plane

    __shared__ float Qs[HP * WP];     // [h][w]
    __shared__ float Vs[HP * WP];     // [h][w]
    __shared__ float KTs[WP * 65];    // [w][h], padded
    __shared__ float kTs[WP * 33];    // [w][g], pooled K, padded
    __shared__ float qs[HG * WP];     // [g][w], pooled Q
    __shared__ float Kqvs[HG * WP];   // [g][w]

    const int t    = threadIdx.x;
    const int warp = t >> 5;
    const int lane = t & 31;
    const unsigned FULL = 0xffffffffu;

    #pragma unroll
    for (int i = 0; i < 2; ++i) {
        int idx = (t + i * 256) * 4;
        float4 qv = *(const float4*)(Qp + idx);
        float4 vv = *(const float4*)(Vp + idx);
        float4 kv = *(const float4*)(Kp + idx);
        *(float4*)(Qs + idx) = qv;
        *(float4*)(Vs + idx) = vv;
        int h = idx >> 5, w = idx & 31;
        KTs[(w + 0) * 65 + h] = kv.x;
        KTs[(w + 1) * 65 + h] = kv.y;
        KTs[(w + 2) * 65 + h] = kv.z;
        KTs[(w + 3) * 65 + h] = kv.w;
    }
    __syncthreads();

    #pragma unroll
    for (int i = 0; i < 4; ++i) {
        int idx = t + i * 256;
        int g = idx >> 5, w = idx & 31;
        qs[g * 32 + w]  = 0.5f * (Qs[(2 * g) * 32 + w] + Qs[(2 * g + 1) * 32 + w]);
        kTs[w * 33 + g] = 0.5f * (KTs[w * 65 + 2 * g] + KTs[w * 65 + 2 * g + 1]);
    }
    __syncthreads();

    // ---- Phase A: S1[g][h] = qp[g]·K[h]; softmax over h. Warp owns g0..g0+3.
    //      Lane covers h = lane and h = lane + 32. q-rows preloaded to regs. ----
    float preg0[4], preg1[4];   // P1[g0+gi][lane], P1[g0+gi][lane+32]
    const int g0 = warp * 4;
    {
        float qreg[4];
        #pragma unroll
        for (int gi = 0; gi < 4; ++gi) qreg[gi] = qs[(g0 + gi) * 32 + lane];

        float s0[4] = {0, 0, 0, 0}, s1[4] = {0, 0, 0, 0};
        #pragma unroll
        for (int w = 0; w < 32; ++w) {
            float k0 = KTs[w * 65 + lane];
            float k1 = KTs[w * 65 + 32 + lane];
            #pragma unroll
            for (int gi = 0; gi < 4; ++gi) {
                float qv = __shfl_sync(FULL, qreg[gi], w);
                s0[gi] = fmaf(qv, k0, s0[gi]);
                s1[gi] = fmaf(qv, k1, s1[gi]);
            }
        }
        #pragma unroll
        for (int gi = 0; gi < 4; ++gi) {
            float a = s0[gi] * D_SCALE, b = s1[gi] * D_SCALE;
            float m = fmaxf(a, b);
            #pragma unroll
            for (int o = 16; o; o >>= 1) m = fmaxf(m, __shfl_xor_sync(FULL, m, o));
            float e0 = __expf(a - m), e1 = __expf(b - m);
            float sum = e0 + e1;
            #pragma unroll
            for (int o = 16; o; o >>= 1) sum += __shfl_xor_sync(FULL, sum, o);
            float r = __frcp_rn(sum);
            preg0[gi] = e0 * r;
            preg1[gi] = e1 * r;
        }
    }

    // ---- Phase B: Kqv[g0+gi][w] = sum_h P1[g0+gi][h] V[h][w]; lane = w. ----
    {
        float acc[4] = {0, 0, 0, 0};
        #pragma unroll 8
        for (int h = 0; h < 32; ++h) {
            float v = Vs[h * 32 + lane];
            #pragma unroll
            for (int gi = 0; gi < 4; ++gi)
                acc[gi] = fmaf(__shfl_sync(FULL, preg0[gi], h), v, acc[gi]);
        }
        #pragma unroll 8
        for (int h = 0; h < 32; ++h) {
            float v = Vs[(h + 32) * 32 + lane];
            #pragma unroll
            for (int gi = 0; gi < 4; ++gi)
                acc[gi] = fmaf(__shfl_sync(FULL, preg1[gi], h), v, acc[gi]);
        }
        #pragma unroll
        for (int gi = 0; gi < 4; ++gi)
            Kqvs[(g0 + gi) * 32 + lane] = acc[gi];
    }
    __syncthreads();

    // ---- Phase C: S2[h][g] = Q[h]·kp[g]; softmax over g. Warp owns h0..h0+7.
    //      Lane = g. Q-rows preloaded to regs. ----
    const int h0 = warp * 8;
    float p2reg[8];             // P2[h0+hi][lane]
    {
        float Qreg[8];
        #pragma unroll
        for (int hi = 0; hi < 8; ++hi) Qreg[hi] = Qs[(h0 + hi) * 32 + lane];

        float s[8] = {0, 0, 0, 0, 0, 0, 0, 0};
        #pragma unroll
        for (int w = 0; w < 32; ++w) {
            float kt = kTs[w * 33 + lane];
            #pragma unroll
            for (int hi = 0; hi < 8; ++hi)
                s[hi] = fmaf(__shfl_sync(FULL, Qreg[hi], w), kt, s[hi]);
        }
        #pragma unroll
        for (int hi = 0; hi < 8; ++hi) {
            float a = s[hi] * D_SCALE;
            float m = a;
            #pragma unroll
            for (int o = 16; o; o >>= 1) m = fmaxf(m, __shfl_xor_sync(FULL, m, o));
            float e = __expf(a - m);
            float sum = e;
            #pragma unroll
            for (int o = 16; o; o >>= 1) sum += __shfl_xor_sync(FULL, sum, o);
            p2reg[hi] = e * __frcp_rn(sum);
        }
    }

    // ---- Phase D: out[h0+hi][w] = sum_g P2[h0+hi][g] Kqv[g][w]; lane = w. ----
    {
        float acc[8] = {0, 0, 0, 0, 0, 0, 0, 0};
        #pragma unroll 8
        for (int g = 0; g < 32; ++g) {
            float kv = Kqvs[g * 32 + lane];
            #pragma unroll
            for (int hi = 0; hi < 8; ++hi)
                acc[hi] = fmaf(__shfl_sync(FULL, p2reg[hi], g), kv, acc[hi]);
        }
        #pragma unroll
        for (int hi = 0; hi < 8; ++hi)
            Op[(h0 + hi) * 32 + lane] = acc[hi];
    }
}

// ---------------------------------------------------------------------------
// Kernel 3: [B, C, N] -> [B, N, C] transpose (output epilogue).
// ---------------------------------------------------------------------------
__global__ __launch_bounds__(256) void transpose_kernel(float* __restrict__ out)
{
    __shared__ float tile[32][33];
    const int b  = blockIdx.z;
    const int c0 = blockIdx.y * 32;
    const int n0 = blockIdx.x * 32;
    const int tx = threadIdx.x;
    const int ty = threadIdx.y;

    const float* src = g_VT + (size_t)b * CDIM * NSEQ;
    #pragma unroll
    for (int i = 0; i < 32; i += 8)
        tile[ty + i][tx] = src[(size_t)(c0 + ty + i) * NSEQ + n0 + tx];
    __syncthreads();
    #pragma unroll
    for (int i = 0; i < 32; i += 8)
        out[((size_t)b * NSEQ + n0 + ty + i) * CDIM + c0 + tx] = tile[tx][ty + i];
}

// ---------------------------------------------------------------------------
extern "C" void kernel_launch(void* const* d_in, const int* in_sizes, int n_in,
                              void* d_out, int out_size)
{
    (void)in_sizes; (void)n_in; (void)out_size;
    const float* X  = (const float*)d_in[0];
    const float* Wq = (const float*)d_in[1];
    const float* bq = (const float*)d_in[2];
    const float* Wk = (const float*)d_in[3];
    const float* bk = (const float*)d_in[4];
    const float* Wv = (const float*)d_in[5];
    const float* bv = (const float*)d_in[6];
    float* out = (float*)d_out;

    const size_t proj_smem = (size_t)2 * 128 * SSTR * sizeof(float);  // 135168 B
    cudaFuncSetAttribute(proj_mma_kernel, cudaFuncAttributeMaxDynamicSharedMemorySize,
                         (int)proj_smem);

    prep_w_kernel<<<dim3(3, 1, 1), 256>>>(Wq, Wk, Wv);
    proj_mma_kernel<<<dim3(1024, 1, 1), 512, proj_smem>>>(X, bq, bk, bv);
    attn_kernel<<<dim3(BATCH * CDIM, 1, 1), 256>>>();
    transpose_kernel<<<dim3(NSEQ / 32, CDIM / 32, BATCH), dim3(32, 8, 1)>>>(out);
}

// round 10
// speedup vs baseline: 1.1695x; 1.1695x over previous
#include <cuda_runtime.h>
#include <cuda_fp16.h>
#include <cstdint>

#define BATCH 64
#define NSEQ  2048
#define CDIM  128
#define HP    64
#define WP    32
#define HG    32   // HP / POOL
#define D_SCALE 0.08838834764831845f  // 1/sqrt(128)

// Scratch: Q,K,V in [B, C, N] (spatial-major) layout. V plane is overwritten
// with the attention output by attn_kernel (each CTA exclusively owns its plane,
// and proj writes it fully on every graph replay -> deterministic).
__device__ float g_QT[(size_t)BATCH * CDIM * NSEQ];
__device__ float g_KT[(size_t)BATCH * CDIM * NSEQ];
__device__ float g_VT[(size_t)BATCH * CDIM * NSEQ];

// Precomputed W fragments (fp16 hi only): [p][(nt*8+ks)*32+lane] -> uint2 (b0, b1)
__device__ uint2 g_Wpk[3 * 4096];

#define SSTR 132   // proj smem row stride (floats)

__device__ __forceinline__ uint32_t h2u(__half2 h) {
    return *reinterpret_cast<uint32_t*>(&h);
}

__device__ __forceinline__ void mma_f16(float& d0, float& d1, float& d2, float& d3,
                                        uint32_t a0, uint32_t a1, uint32_t a2, uint32_t a3,
                                        uint32_t b0, uint32_t b1) {
    asm volatile(
        "mma.sync.aligned.m16n8k16.row.col.f32.f16.f16.f32 "
        "{%0,%1,%2,%3}, {%4,%5,%6,%7}, {%8,%9}, {%0,%1,%2,%3};"
        : "+f"(d0), "+f"(d1), "+f"(d2), "+f"(d3)
        : "r"(a0), "r"(a1), "r"(a2), "r"(a3), "r"(b0), "r"(b1));
}

// Split float2 -> fp16 hi (packed) and fp16 lo residual (packed).
__device__ __forceinline__ void f16_split(float e0, float e1,
                                          uint32_t& hi, uint32_t& lo) {
    __half2 h = __floats2half2_rn(e0, e1);
    float2 f = __half22float2(h);
    __half2 l = __floats2half2_rn(e0 - f.x, e1 - f.y);
    hi = h2u(h);
    lo = h2u(l);
}

// ---------------------------------------------------------------------------
// Kernel 0: convert W matrices into MMA-fragment-packed fp16 (hi only), once.
// Slot s of lane gj*4+s: b0 = fp16(k=2s, 2s+1), b1 = fp16(k=2s+8, 2s+9).
// ---------------------------------------------------------------------------
__global__ __launch_bounds__(256) void prep_w_kernel(
    const float* __restrict__ Wq, const float* __restrict__ Wk,
    const float* __restrict__ Wv)
{
    const int p = blockIdx.x;
    const float* W = (p == 0) ? Wq : (p == 1) ? Wk : Wv;
    const int t = threadIdx.x;
    #pragma unroll
    for (int i = 0; i < 16; ++i) {
        const int pos  = t + i * 256;        // 0..4095
        const int lane = pos & 31;
        const int ks   = (pos >> 5) & 7;
        const int nt   = pos >> 8;
        const int gj   = lane >> 2;
        const int s    = lane & 3;
        const int j    = nt * 8 + gj;
        const int c0   = ks * 16 + 2 * s;
        __half2 b0 = __floats2half2_rn(W[j * CDIM + c0],     W[j * CDIM + c0 + 1]);
        __half2 b1 = __floats2half2_rn(W[j * CDIM + c0 + 8], W[j * CDIM + c0 + 9]);
        g_Wpk[p * 4096 + pos] = make_uint2(h2u(b0), h2u(b1));
    }
}

// ---------------------------------------------------------------------------
// Kernel 1: projection GEMMs, fp16 2-term split (Ahi*Bhi + Alo*Bhi; the dropped
// Ahi*Blo term is ~2^-12 relative). 512 threads = 16 warps:
// warp = (mgroup 0..7) x (nhalf 0..1). W fragments copied from precomputed
// global (fp16 hi only -> LDS.64 per nt feeds 2 MMAs).
// Out[m,j] = sigmoid(sum_c X[m,c] W[j,c] + b[j]), stored transposed OutT[b][j][n].
// ---------------------------------------------------------------------------
__global__ __launch_bounds__(512) void proj_mma_kernel(
    const float* __restrict__ X,
    const float* __restrict__ bq, const float* __restrict__ bk,
    const float* __restrict__ bv)
{
    extern __shared__ float sm[];
    float* Xs  = sm;                        // [m][c] 128 x SSTR fp32 (67.6 KB)
    uint2* Wpk = (uint2*)(sm + 128 * SSTR); // [16 nt][8 ks][32 lane] uint2 (32 KB)
    // epilogue transpose buffer T aliases the Wpk region (67.6 KB allocated)

    const int t    = threadIdx.x;
    const int warp = t >> 5;
    const int lane = t & 31;
    const int M0   = blockIdx.x * 128;
    const int bidx = M0 >> 11;
    const int n0   = M0 & 2047;

    {
        const int r  = t >> 5;
        const int c4 = (t & 31) << 2;
        #pragma unroll
        for (int it = 0; it < 8; ++it) {
            const int row = it * 16 + r;
            float4 xv = *(const float4*)(X + (size_t)(M0 + row) * CDIM + c4);
            *(float4*)(Xs + row * SSTR + c4) = xv;
        }
    }

    const int g      = lane >> 2;
    const int tid    = lane & 3;
    const int mgroup = warp & 7;
    const int nhalf  = warp >> 3;
    const int mbase  = mgroup * 16;

    #pragma unroll 1
    for (int p = 0; p < 3; ++p) {
        const float* bias = (p == 0) ? bq : (p == 1) ? bk : bv;
        float* OutT       = (p == 0) ? g_QT : (p == 1) ? g_KT : g_VT;

        __syncthreads();   // prev epilogue done with Wpk region; Xs stable

        // ---- Stage W fragments: straight copy (4096 uint2 = 2048 uint4) ----
        {
            const uint4* src = (const uint4*)&g_Wpk[p * 4096];
            uint4* dst = (uint4*)Wpk;
            #pragma unroll
            for (int i = 0; i < 4; ++i)
                dst[t + i * 512] = src[t + i * 512];
        }
        __syncthreads();

        // ---- MMA mainloop: warp owns 16 m-rows x 64 j-cols (8 nt) ----
        float acc[8][4];
        #pragma unroll
        for (int nt = 0; nt < 8; ++nt)
            #pragma unroll
            for (int q = 0; q < 4; ++q) acc[nt][q] = 0.0f;

        #pragma unroll
        for (int ks = 0; ks < 8; ++ks) {
            const int c0 = ks * 16 + 2 * tid;
            const float* xr0 = Xs + (mbase + g) * SSTR + c0;
            const float* xr1 = Xs + (mbase + g + 8) * SSTR + c0;
            float2 x00 = *(const float2*)(xr0);
            float2 x02 = *(const float2*)(xr0 + 8);
            float2 x10 = *(const float2*)(xr1);
            float2 x12 = *(const float2*)(xr1 + 8);
            uint32_t ah0, al0, ah1, al1, ah2, al2, ah3, al3;
            f16_split(x00.x, x00.y, ah0, al0);
            f16_split(x10.x, x10.y, ah1, al1);
            f16_split(x02.x, x02.y, ah2, al2);
            f16_split(x12.x, x12.y, ah3, al3);

            #pragma unroll
            for (int nt = 0; nt < 8; ++nt) {
                const int ntg = nhalf * 8 + nt;
                uint2 w = Wpk[(ntg * 8 + ks) * 32 + lane];
                mma_f16(acc[nt][0], acc[nt][1], acc[nt][2], acc[nt][3],
                        ah0, ah1, ah2, ah3, w.x, w.y);
                mma_f16(acc[nt][0], acc[nt][1], acc[nt][2], acc[nt][3],
                        al0, al1, al2, al3, w.x, w.y);
            }
        }

        __syncthreads();   // all warps done reading Wpk -> reuse as transpose buf

        // ---- Epilogue: bias + sigmoid, transpose to [j][m] via smem ----
        float* T = (float*)Wpk;
        #pragma unroll
        for (int nt = 0; nt < 8; ++nt) {
            const int j0 = nhalf * 64 + nt * 8 + 2 * tid;
            const float b0v = __ldg(bias + j0);
            const float b1v = __ldg(bias + j0 + 1);
            float v0 = acc[nt][0] + b0v;
            float v1 = acc[nt][1] + b1v;
            float v2 = acc[nt][2] + b0v;
            float v3 = acc[nt][3] + b1v;
            v0 = 1.0f / (1.0f + __expf(-v0));
            v1 = 1.0f / (1.0f + __expf(-v1));
            v2 = 1.0f / (1.0f + __expf(-v2));
            v3 = 1.0f / (1.0f + __expf(-v3));
            T[j0 * SSTR + mbase + g]           = v0;
            T[(j0 + 1) * SSTR + mbase + g]     = v1;
            T[j0 * SSTR + mbase + g + 8]       = v2;
            T[(j0 + 1) * SSTR + mbase + g + 8] = v3;
        }
        __syncthreads();

        // ---- Coalesced float4 store: OutT[bidx][j][n0 + m] ----
        #pragma unroll
        for (int it = 0; it < 8; ++it) {
            const int idx = t + it * 512;
            const int j   = idx >> 5;
            const int m4  = (idx & 31) << 2;
            float4 v = *(const float4*)(T + j * SSTR + m4);
            *(float4*)(OutT + ((size_t)bidx * CDIM + j) * NSEQ + n0 + m4) = v;
        }
    }
}

// ---------------------------------------------------------------------------
// Kernel 2: per-(b,c) dual-softmax attention on a [64,32] plane (proven R4).
// ---------------------------------------------------------------------------
__global__ __launch_bounds__(256) void attn_kernel()
{
    const int bc = blockIdx.x;                      // b*128 + c
    const float* Qp = g_QT + (size_t)bc * NSEQ;
    const float* Kp = g_KT + (size_t)bc * NSEQ;
    const float* Vp = g_VT + (size_t)bc * NSEQ;
    float* Op = g_VT + (size_t)bc * NSEQ;           // overwrite V plane

    __shared__ float Qs[HP * WP];     // [h][w]
    __shared__ float Vs[HP * WP];     // [h][w]
    __shared__ float KTs[WP * 65];    // [w][h], padded
    __shared__ float kTs[WP * 33];    // [w][g], pooled K, padded
    __shared__ float qs[HG * WP];     // [g][w], pooled Q
    __shared__ float Kqvs[HG * WP];   // [g][w]
    __shared__ float buf[8][264];     // per-warp softmax rows

    const int t    = threadIdx.x;
    const int warp = t >> 5;
    const int lane = t & 31;

    #pragma unroll
    for (int i = 0; i < 2; ++i) {
        int idx = (t + i * 256) * 4;
        float4 qv = *(const float4*)(Qp + idx);
        float4 vv = *(const float4*)(Vp + idx);
        float4 kv = *(const float4*)(Kp + idx);
        *(float4*)(Qs + idx) = qv;
        *(float4*)(Vs + idx) = vv;
        int h = idx >> 5, w = idx & 31;
        KTs[(w + 0) * 65 + h] = kv.x;
        KTs[(w + 1) * 65 + h] = kv.y;
        KTs[(w + 2) * 65 + h] = kv.z;
        KTs[(w + 3) * 65 + h] = kv.w;
    }
    __syncthreads();

    #pragma unroll
    for (int i = 0; i < 4; ++i) {
        int idx = t + i * 256;
        int g = idx >> 5, w = idx & 31;
        qs[g * 32 + w]  = 0.5f * (Qs[(2 * g) * 32 + w] + Qs[(2 * g + 1) * 32 + w]);
        kTs[w * 33 + g] = 0.5f * (KTs[w * 65 + 2 * g] + KTs[w * 65 + 2 * g + 1]);
    }
    __syncthreads();

    // ---- Kq = softmax_h(scale * q @ K^T), Kqv = Kq @ V ----
    {
        const int g0 = warp * 4;
        float s0[4] = {0, 0, 0, 0}, s1[4] = {0, 0, 0, 0};
        #pragma unroll
        for (int w = 0; w < 32; ++w) {
            float k0 = KTs[w * 65 + lane];
            float k1 = KTs[w * 65 + 32 + lane];
            #pragma unroll
            for (int gi = 0; gi < 4; ++gi) {
                float qv = qs[(g0 + gi) * 32 + w];
                s0[gi] = fmaf(qv, k0, s0[gi]);
                s1[gi] = fmaf(qv, k1, s1[gi]);
            }
        }
        #pragma unroll
        for (int gi = 0; gi < 4; ++gi) {
            float a = s0[gi] * D_SCALE, b = s1[gi] * D_SCALE;
            float m = fmaxf(a, b);
            #pragma unroll
            for (int o = 16; o; o >>= 1) m = fmaxf(m, __shfl_xor_sync(0xffffffffu, m, o));
            float e0 = __expf(a - m), e1 = __expf(b - m);
            float sum = e0 + e1;
            #pragma unroll
            for (int o = 16; o; o >>= 1) sum += __shfl_xor_sync(0xffffffffu, sum, o);
            float r = __frcp_rn(sum);
            buf[warp][gi * 66 + lane]      = e0 * r;
            buf[warp][gi * 66 + 32 + lane] = e1 * r;
        }
        __syncwarp();
        const int gi = lane >> 3;
        const int w4 = (lane & 7) << 2;
        float4 acc = {0, 0, 0, 0};
        #pragma unroll 8
        for (int h = 0; h < 64; ++h) {
            float p  = buf[warp][gi * 66 + h];
            float4 v = *(const float4*)(Vs + h * 32 + w4);
            acc.x = fmaf(p, v.x, acc.x);
            acc.y = fmaf(p, v.y, acc.y);
            acc.z = fmaf(p, v.z, acc.z);
            acc.w = fmaf(p, v.w, acc.w);
        }
        *(float4*)(Kqvs + (g0 + gi) * 32 + w4) = acc;
    }
    __syncthreads();

    // ---- Qk = softmax_g(scale * Q @ k^T), out = Qk @ Kqv ----
    {
        const int h0 = warp * 8;
        float s[8] = {0, 0, 0, 0, 0, 0, 0, 0};
        #pragma unroll
        for (int w = 0; w < 32; ++w) {
            float kt = kTs[w * 33 + lane];
            #pragma unroll
            for (int hi = 0; hi < 8; ++hi)
                s[hi] = fmaf(Qs[(h0 + hi) * 32 + w], kt, s[hi]);
        }
        #pragma unroll
        for (int hi = 0; hi < 8; ++hi) {
            float a = s[hi] * D_SCALE;
            float m = a;
            #pragma unroll
            for (int o = 16; o; o >>= 1) m = fmaxf(m, __shfl_xor_sync(0xffffffffu, m, o));
            float e = __expf(a - m);
            float sum = e;
            #pragma unroll
            for (int o = 16; o; o >>= 1) sum += __shfl_xor_sync(0xffffffffu, sum, o);
            buf[warp][hi * 33 + lane] = e * __frcp_rn(sum);
        }
        __syncwarp();
        const int hi = lane >> 2;
        const int w8 = (lane & 3) << 3;
        float4 acc0 = {0, 0, 0, 0}, acc1 = {0, 0, 0, 0};
        #pragma unroll 8
        for (int g = 0; g < 32; ++g) {
            float p   = buf[warp][hi * 33 + g];
            float4 v0 = *(const float4*)(Kqvs + g * 32 + w8);
            float4 v1 = *(const float4*)(Kqvs + g * 32 + w8 + 4);
            acc0.x = fmaf(p, v0.x, acc0.x);
            acc0.y = fmaf(p, v0.y, acc0.y);
            acc0.z = fmaf(p, v0.z, acc0.z);
            acc0.w = fmaf(p, v0.w, acc0.w);
            acc1.x = fmaf(p, v1.x, acc1.x);
            acc1.y = fmaf(p, v1.y, acc1.y);
            acc1.z = fmaf(p, v1.z, acc1.z);
            acc1.w = fmaf(p, v1.w, acc1.w);
        }
        float* dst = Op + (h0 + hi) * 32 + w8;
        *(float4*)(dst)     = acc0;
        *(float4*)(dst + 4) = acc1;
    }
}

// ---------------------------------------------------------------------------
// Kernel 3: [B, C, N] -> [B, N, C] transpose (output epilogue).
// ---------------------------------------------------------------------------
__global__ __launch_bounds__(256) void transpose_kernel(float* __restrict__ out)
{
    __shared__ float tile[32][33];
    const int b  = blockIdx.z;
    const int c0 = blockIdx.y * 32;
    const int n0 = blockIdx.x * 32;
    const int tx = threadIdx.x;
    const int ty = threadIdx.y;

    const float* src = g_VT + (size_t)b * CDIM * NSEQ;
    #pragma unroll
    for (int i = 0; i < 32; i += 8)
        tile[ty + i][tx] = src[(size_t)(c0 + ty + i) * NSEQ + n0 + tx];
    __syncthreads();
    #pragma unroll
    for (int i = 0; i < 32; i += 8)
        out[((size_t)b * NSEQ + n0 + ty + i) * CDIM + c0 + tx] = tile[tx][ty + i];
}

// ---------------------------------------------------------------------------
extern "C" void kernel_launch(void* const* d_in, const int* in_sizes, int n_in,
                              void* d_out, int out_size)
{
    (void)in_sizes; (void)n_in; (void)out_size;
    const float* X  = (const float*)d_in[0];
    const float* Wq = (const float*)d_in[1];
    const float* bq = (const float*)d_in[2];
    const float* Wk = (const float*)d_in[3];
    const float* bk = (const float*)d_in[4];
    const float* Wv = (const float*)d_in[5];
    const float* bv = (const float*)d_in[6];
    float* out = (float*)d_out;

    const size_t proj_smem = (size_t)2 * 128 * SSTR * sizeof(float);  // 135168 B
    cudaFuncSetAttribute(proj_mma_kernel, cudaFuncAttributeMaxDynamicSharedMemorySize,
                         (int)proj_smem);

    prep_w_kernel<<<dim3(3, 1, 1), 256>>>(Wq, Wk, Wv);
    proj_mma_kernel<<<dim3(1024, 1, 1), 512, proj_smem>>>(X, bq, bk, bv);
    attn_kernel<<<dim3(BATCH * CDIM, 1, 1), 256>>>();
    transpose_kernel<<<dim3(NSEQ / 32, CDIM / 32, BATCH), dim3(32, 8, 1)>>>(out);
}

// round 11
// speedup vs baseline: 1.2257x; 1.0481x over previous
#include <cuda_runtime.h>
#include <cuda_fp16.h>
#include <cstdint>

#define BATCH 64
#define NSEQ  2048
#define CDIM  128
#define HP    64
#define WP    32
#define HG    32   // HP / POOL
#define D_SCALE 0.08838834764831845f  // 1/sqrt(128)

// Scratch: Q,K,V in [B, C, N] (spatial-major) layout. V plane is overwritten
// with the attention output by attn_kernel (each CTA exclusively owns its plane,
// and proj writes it fully on every graph replay -> deterministic).
__device__ float g_QT[(size_t)BATCH * CDIM * NSEQ];
__device__ float g_KT[(size_t)BATCH * CDIM * NSEQ];
__device__ float g_VT[(size_t)BATCH * CDIM * NSEQ];

// Precomputed W fragments (fp16): [p][(nt*8+ks)*32+lane] -> uint2 (b0, b1)
__device__ uint2 g_Wpk[3 * 4096];

#define SSTR 132   // proj smem row stride (floats)

__device__ __forceinline__ uint32_t h2u(__half2 h) {
    return *reinterpret_cast<uint32_t*>(&h);
}

__device__ __forceinline__ void mma_f16(float& d0, float& d1, float& d2, float& d3,
                                        uint32_t a0, uint32_t a1, uint32_t a2, uint32_t a3,
                                        uint32_t b0, uint32_t b1) {
    asm volatile(
        "mma.sync.aligned.m16n8k16.row.col.f32.f16.f16.f32 "
        "{%0,%1,%2,%3}, {%4,%5,%6,%7}, {%8,%9}, {%0,%1,%2,%3};"
        : "+f"(d0), "+f"(d1), "+f"(d2), "+f"(d3)
        : "r"(a0), "r"(a1), "r"(a2), "r"(a3), "r"(b0), "r"(b1));
}

// ---------------------------------------------------------------------------
// Kernel 0: convert W matrices into MMA-fragment-packed fp16, once.
// Slot s of lane gj*4+s: b0 = fp16(k=2s, 2s+1), b1 = fp16(k=2s+8, 2s+9).
// ---------------------------------------------------------------------------
__global__ __launch_bounds__(256) void prep_w_kernel(
    const float* __restrict__ Wq, const float* __restrict__ Wk,
    const float* __restrict__ Wv)
{
    const int p = blockIdx.x;
    const float* W = (p == 0) ? Wq : (p == 1) ? Wk : Wv;
    const int t = threadIdx.x;
    #pragma unroll
    for (int i = 0; i < 16; ++i) {
        const int pos  = t + i * 256;        // 0..4095
        const int lane = pos & 31;
        const int ks   = (pos >> 5) & 7;
        const int nt   = pos >> 8;
        const int gj   = lane >> 2;
        const int s    = lane & 3;
        const int j    = nt * 8 + gj;
        const int c0   = ks * 16 + 2 * s;
        __half2 b0 = __floats2half2_rn(W[j * CDIM + c0],     W[j * CDIM + c0 + 1]);
        __half2 b1 = __floats2half2_rn(W[j * CDIM + c0 + 8], W[j * CDIM + c0 + 9]);
        g_Wpk[p * 4096 + pos] = make_uint2(h2u(b0), h2u(b1));
    }
}

// ---------------------------------------------------------------------------
// Kernel 1: projection GEMMs, single-term fp16 (A and W both rounded to fp16;
// measured error budget from R10 shows ~40x margin vs the 1e-3 gate).
// 512 threads = 16 warps: warp = (mgroup 0..7) x (nhalf 0..1).
// Out[m,j] = sigmoid(sum_c X[m,c] W[j,c] + b[j]), stored transposed OutT[b][j][n].
// ---------------------------------------------------------------------------
__global__ __launch_bounds__(512) void proj_mma_kernel(
    const float* __restrict__ X,
    const float* __restrict__ bq, const float* __restrict__ bk,
    const float* __restrict__ bv)
{
    extern __shared__ float sm[];
    float* Xs  = sm;                        // [m][c] 128 x SSTR fp32 (67.6 KB)
    uint2* Wpk = (uint2*)(sm + 128 * SSTR); // [16 nt][8 ks][32 lane] uint2 (32 KB)
    // epilogue transpose buffer T aliases the Wpk region (67.6 KB allocated)

    const int t    = threadIdx.x;
    const int warp = t >> 5;
    const int lane = t & 31;
    const int M0   = blockIdx.x * 128;
    const int bidx = M0 >> 11;
    const int n0   = M0 & 2047;

    {
        const int r  = t >> 5;
        const int c4 = (t & 31) << 2;
        #pragma unroll
        for (int it = 0; it < 8; ++it) {
            const int row = it * 16 + r;
            float4 xv = *(const float4*)(X + (size_t)(M0 + row) * CDIM + c4);
            *(float4*)(Xs + row * SSTR + c4) = xv;
        }
    }

    const int g      = lane >> 2;
    const int tid    = lane & 3;
    const int mgroup = warp & 7;
    const int nhalf  = warp >> 3;
    const int mbase  = mgroup * 16;

    #pragma unroll 1
    for (int p = 0; p < 3; ++p) {
        const float* bias = (p == 0) ? bq : (p == 1) ? bk : bv;
        float* OutT       = (p == 0) ? g_QT : (p == 1) ? g_KT : g_VT;

        __syncthreads();   // prev epilogue done with Wpk region; Xs stable

        // ---- Stage W fragments: straight copy (4096 uint2 = 2048 uint4) ----
        {
            const uint4* src = (const uint4*)&g_Wpk[p * 4096];
            uint4* dst = (uint4*)Wpk;
            #pragma unroll
            for (int i = 0; i < 4; ++i)
                dst[t + i * 512] = src[t + i * 512];
        }
        __syncthreads();

        // ---- MMA mainloop: warp owns 16 m-rows x 64 j-cols (8 nt) ----
        float acc[8][4];
        #pragma unroll
        for (int nt = 0; nt < 8; ++nt)
            #pragma unroll
            for (int q = 0; q < 4; ++q) acc[nt][q] = 0.0f;

        #pragma unroll
        for (int ks = 0; ks < 8; ++ks) {
            const int c0 = ks * 16 + 2 * tid;
            const float* xr0 = Xs + (mbase + g) * SSTR + c0;
            const float* xr1 = Xs + (mbase + g + 8) * SSTR + c0;
            float2 x00 = *(const float2*)(xr0);
            float2 x02 = *(const float2*)(xr0 + 8);
            float2 x10 = *(const float2*)(xr1);
            float2 x12 = *(const float2*)(xr1 + 8);
            uint32_t a0 = h2u(__floats2half2_rn(x00.x, x00.y));
            uint32_t a1 = h2u(__floats2half2_rn(x10.x, x10.y));
            uint32_t a2 = h2u(__floats2half2_rn(x02.x, x02.y));
            uint32_t a3 = h2u(__floats2half2_rn(x12.x, x12.y));

            #pragma unroll
            for (int nt = 0; nt < 8; ++nt) {
                const int ntg = nhalf * 8 + nt;
                uint2 w = Wpk[(ntg * 8 + ks) * 32 + lane];
                mma_f16(acc[nt][0], acc[nt][1], acc[nt][2], acc[nt][3],
                        a0, a1, a2, a3, w.x, w.y);
            }
        }

        __syncthreads();   // all warps done reading Wpk -> reuse as transpose buf

        // ---- Epilogue: bias + sigmoid, transpose to [j][m] via smem ----
        float* T = (float*)Wpk;
        #pragma unroll
        for (int nt = 0; nt < 8; ++nt) {
            const int j0 = nhalf * 64 + nt * 8 + 2 * tid;
            const float b0v = __ldg(bias + j0);
            const float b1v = __ldg(bias + j0 + 1);
            float v0 = acc[nt][0] + b0v;
            float v1 = acc[nt][1] + b1v;
            float v2 = acc[nt][2] + b0v;
            float v3 = acc[nt][3] + b1v;
            v0 = 1.0f / (1.0f + __expf(-v0));
            v1 = 1.0f / (1.0f + __expf(-v1));
            v2 = 1.0f / (1.0f + __expf(-v2));
            v3 = 1.0f / (1.0f + __expf(-v3));
            T[j0 * SSTR + mbase + g]           = v0;
            T[(j0 + 1) * SSTR + mbase + g]     = v1;
            T[j0 * SSTR + mbase + g + 8]       = v2;
            T[(j0 + 1) * SSTR + mbase + g + 8] = v3;
        }
        __syncthreads();

        // ---- Coalesced float4 store: OutT[bidx][j][n0 + m] ----
        #pragma unroll
        for (int it = 0; it < 8; ++it) {
            const int idx = t + it * 512;
            const int j   = idx >> 5;
            const int m4  = (idx & 31) << 2;
            float4 v = *(const float4*)(T + j * SSTR + m4);
            *(float4*)(OutT + ((size_t)bidx * CDIM + j) * NSEQ + n0 + m4) = v;
        }
    }
}

// ---------------------------------------------------------------------------
// Kernel 2: per-(b,c) dual-softmax attention on a [64,32] plane (proven R4).
// ---------------------------------------------------------------------------
__global__ __launch_bounds__(256) void attn_kernel()
{
    const int bc = blockIdx.x;                      // b*128 + c
    const float* Qp = g_QT + (size_t)bc * NSEQ;
    const float* Kp = g_KT + (size_t)bc * NSEQ;
    const float* Vp = g_VT + (size_t)bc * NSEQ;
    float* Op = g_VT + (size_t)bc * NSEQ;           // overwrite V plane

    __shared__ float Qs[HP * WP];     // [h][w]
    __shared__ float Vs[HP * WP];     // [h][w]
    __shared__ float KTs[WP * 65];    // [w][h], padded
    __shared__ float kTs[WP * 33];    // [w][g], pooled K, padded
    __shared__ float qs[HG * WP];     // [g][w], pooled Q
    __shared__ float Kqvs[HG * WP];   // [g][w]
    __shared__ float buf[8][264];     // per-warp softmax rows

    const int t    = threadIdx.x;
    const int warp = t >> 5;
    const int lane = t & 31;

    #pragma unroll
    for (int i = 0; i < 2; ++i) {
        int idx = (t + i * 256) * 4;
        float4 qv = *(const float4*)(Qp + idx);
        float4 vv = *(const float4*)(Vp + idx);
        float4 kv = *(const float4*)(Kp + idx);
        *(float4*)(Qs + idx) = qv;
        *(float4*)(Vs + idx) = vv;
        int h = idx >> 5, w = idx & 31;
        KTs[(w + 0) * 65 + h] = kv.x;
        KTs[(w + 1) * 65 + h] = kv.y;
        KTs[(w + 2) * 65 + h] = kv.z;
        KTs[(w + 3) * 65 + h] = kv.w;
    }
    __syncthreads();

    #pragma unroll
    for (int i = 0; i < 4; ++i) {
        int idx = t + i * 256;
        int g = idx >> 5, w = idx & 31;
        qs[g * 32 + w]  = 0.5f * (Qs[(2 * g) * 32 + w] + Qs[(2 * g + 1) * 32 + w]);
        kTs[w * 33 + g] = 0.5f * (KTs[w * 65 + 2 * g] + KTs[w * 65 + 2 * g + 1]);
    }
    __syncthreads();

    // ---- Kq = softmax_h(scale * q @ K^T), Kqv = Kq @ V ----
    {
        const int g0 = warp * 4;
        float s0[4] = {0, 0, 0, 0}, s1[4] = {0, 0, 0, 0};
        #pragma unroll
        for (int w = 0; w < 32; ++w) {
            float k0 = KTs[w * 65 + lane];
            float k1 = KTs[w * 65 + 32 + lane];
            #pragma unroll
            for (int gi = 0; gi < 4; ++gi) {
                float qv = qs[(g0 + gi) * 32 + w];
                s0[gi] = fmaf(qv, k0, s0[gi]);
                s1[gi] = fmaf(qv, k1, s1[gi]);
            }
        }
        #pragma unroll
        for (int gi = 0; gi < 4; ++gi) {
            float a = s0[gi] * D_SCALE, b = s1[gi] * D_SCALE;
            float m = fmaxf(a, b);
            #pragma unroll
            for (int o = 16; o; o >>= 1) m = fmaxf(m, __shfl_xor_sync(0xffffffffu, m, o));
            float e0 = __expf(a - m), e1 = __expf(b - m);
            float sum = e0 + e1;
            #pragma unroll
            for (int o = 16; o; o >>= 1) sum += __shfl_xor_sync(0xffffffffu, sum, o);
            float r = __frcp_rn(sum);
            buf[warp][gi * 66 + lane]      = e0 * r;
            buf[warp][gi * 66 + 32 + lane] = e1 * r;
        }
        __syncwarp();
        const int gi = lane >> 3;
        const int w4 = (lane & 7) << 2;
        float4 acc = {0, 0, 0, 0};
        #pragma unroll 8
        for (int h = 0; h < 64; ++h) {
            float p  = buf[warp][gi * 66 + h];
            float4 v = *(const float4*)(Vs + h * 32 + w4);
            acc.x = fmaf(p, v.x, acc.x);
            acc.y = fmaf(p, v.y, acc.y);
            acc.z = fmaf(p, v.z, acc.z);
            acc.w = fmaf(p, v.w, acc.w);
        }
        *(float4*)(Kqvs + (g0 + gi) * 32 + w4) = acc;
    }
    __syncthreads();

    // ---- Qk = softmax_g(scale * Q @ k^T), out = Qk @ Kqv ----
    {
        const int h0 = warp * 8;
        float s[8] = {0, 0, 0, 0, 0, 0, 0, 0};
        #pragma unroll
        for (int w = 0; w < 32; ++w) {
            float kt = kTs[w * 33 + lane];
            #pragma unroll
            for (int hi = 0; hi < 8; ++hi)
                s[hi] = fmaf(Qs[(h0 + hi) * 32 + w], kt, s[hi]);
        }
        #pragma unroll
        for (int hi = 0; hi < 8; ++hi) {
            float a = s[hi] * D_SCALE;
            float m = a;
            #pragma unroll
            for (int o = 16; o; o >>= 1) m = fmaxf(m, __shfl_xor_sync(0xffffffffu, m, o));
            float e = __expf(a - m);
            float sum = e;
            #pragma unroll
            for (int o = 16; o; o >>= 1) sum += __shfl_xor_sync(0xffffffffu, sum, o);
            buf[warp][hi * 33 + lane] = e * __frcp_rn(sum);
        }
        __syncwarp();
        const int hi = lane >> 2;
        const int w8 = (lane & 3) << 3;
        float4 acc0 = {0, 0, 0, 0}, acc1 = {0, 0, 0, 0};
        #pragma unroll 8
        for (int g = 0; g < 32; ++g) {
            float p   = buf[warp][hi * 33 + g];
            float4 v0 = *(const float4*)(Kqvs + g * 32 + w8);
            float4 v1 = *(const float4*)(Kqvs + g * 32 + w8 + 4);
            acc0.x = fmaf(p, v0.x, acc0.x);
            acc0.y = fmaf(p, v0.y, acc0.y);
            acc0.z = fmaf(p, v0.z, acc0.z);
            acc0.w = fmaf(p, v0.w, acc0.w);
            acc1.x = fmaf(p, v1.x, acc1.x);
            acc1.y = fmaf(p, v1.y, acc1.y);
            acc1.z = fmaf(p, v1.z, acc1.z);
            acc1.w = fmaf(p, v1.w, acc1.w);
        }
        float* dst = Op + (h0 + hi) * 32 + w8;
        *(float4*)(dst)     = acc0;
        *(float4*)(dst + 4) = acc1;
    }
}

// ---------------------------------------------------------------------------
// Kernel 3: [B, C, N] -> [B, N, C] transpose (output epilogue).
// ---------------------------------------------------------------------------
__global__ __launch_bounds__(256) void transpose_kernel(float* __restrict__ out)
{
    __shared__ float tile[32][33];
    const int b  = blockIdx.z;
    const int c0 = blockIdx.y * 32;
    const int n0 = blockIdx.x * 32;
    const int tx = threadIdx.x;
    const int ty = threadIdx.y;

    const float* src = g_VT + (size_t)b * CDIM * NSEQ;
    #pragma unroll
    for (int i = 0; i < 32; i += 8)
        tile[ty + i][tx] = src[(size_t)(c0 + ty + i) * NSEQ + n0 + tx];
    __syncthreads();
    #pragma unroll
    for (int i = 0; i < 32; i += 8)
        out[((size_t)b * NSEQ + n0 + ty + i) * CDIM + c0 + tx] = tile[tx][ty + i];
}

// ---------------------------------------------------------------------------
extern "C" void kernel_launch(void* const* d_in, const int* in_sizes, int n_in,
                              void* d_out, int out_size)
{
    (void)in_sizes; (void)n_in; (void)out_size;
    const float* X  = (const float*)d_in[0];
    const float* Wq = (const float*)d_in[1];
    const float* bq = (const float*)d_in[2];
    const float* Wk = (const float*)d_in[3];
    const float* bk = (const float*)d_in[4];
    const float* Wv = (const float*)d_in[5];
    const float* bv = (const float*)d_in[6];
    float* out = (float*)d_out;

    const size_t proj_smem = (size_t)2 * 128 * SSTR * sizeof(float);  // 135168 B
    cudaFuncSetAttribute(proj_mma_kernel, cudaFuncAttributeMaxDynamicSharedMemorySize,
                         (int)proj_smem);

    prep_w_kernel<<<dim3(3, 1, 1), 256>>>(Wq, Wk, Wv);
    proj_mma_kernel<<<dim3(1024, 1, 1), 512, proj_smem>>>(X, bq, bk, bv);
    attn_kernel<<<dim3(BATCH * CDIM, 1, 1), 256>>>();
    transpose_kernel<<<dim3(NSEQ / 32, CDIM / 32, BATCH), dim3(32, 8, 1)>>>(out);
}

// round 12
// speedup vs baseline: 1.2914x; 1.0536x over previous
#include <cuda_runtime.h>
#include <cuda_fp16.h>
#include <cstdint>

#define BATCH 64
#define NSEQ  2048
#define CDIM  128
#define HP    64
#define WP    32
#define HG    32   // HP / POOL
#define D_SCALE 0.08838834764831845f  // 1/sqrt(128)

// Scratch: Q,K,V in [B, C, N] (spatial-major) layout. V plane is overwritten
// with the attention output by attn_kernel (each CTA exclusively owns its plane,
// and proj writes it fully on every graph replay -> deterministic).
__device__ float g_QT[(size_t)BATCH * CDIM * NSEQ];
__device__ float g_KT[(size_t)BATCH * CDIM * NSEQ];
__device__ float g_VT[(size_t)BATCH * CDIM * NSEQ];

// Precomputed W fragments (fp16): [p][(nt*8+ks)*32+lane] -> uint2 (b0, b1)
__device__ uint2 g_Wpk[3 * 4096];

#define SSTR 132   // proj smem row stride (floats)

__device__ __forceinline__ uint32_t h2u(__half2 h) {
    return *reinterpret_cast<uint32_t*>(&h);
}

__device__ __forceinline__ void mma_f16(float& d0, float& d1, float& d2, float& d3,
                                        uint32_t a0, uint32_t a1, uint32_t a2, uint32_t a3,
                                        uint32_t b0, uint32_t b1) {
    asm volatile(
        "mma.sync.aligned.m16n8k16.row.col.f32.f16.f16.f32 "
        "{%0,%1,%2,%3}, {%4,%5,%6,%7}, {%8,%9}, {%0,%1,%2,%3};"
        : "+f"(d0), "+f"(d1), "+f"(d2), "+f"(d3)
        : "r"(a0), "r"(a1), "r"(a2), "r"(a3), "r"(b0), "r"(b1));
}

// ---------------------------------------------------------------------------
// Kernel 0: convert W matrices into MMA-fragment-packed fp16, once.
// ---------------------------------------------------------------------------
__global__ __launch_bounds__(256) void prep_w_kernel(
    const float* __restrict__ Wq, const float* __restrict__ Wk,
    const float* __restrict__ Wv)
{
    const int p = blockIdx.x;
    const float* W = (p == 0) ? Wq : (p == 1) ? Wk : Wv;
    const int t = threadIdx.x;
    #pragma unroll
    for (int i = 0; i < 16; ++i) {
        const int pos  = t + i * 256;        // 0..4095
        const int lane = pos & 31;
        const int ks   = (pos >> 5) & 7;
        const int nt   = pos >> 8;
        const int gj   = lane >> 2;
        const int s    = lane & 3;
        const int j    = nt * 8 + gj;
        const int c0   = ks * 16 + 2 * s;
        __half2 b0 = __floats2half2_rn(W[j * CDIM + c0],     W[j * CDIM + c0 + 1]);
        __half2 b1 = __floats2half2_rn(W[j * CDIM + c0 + 8], W[j * CDIM + c0 + 9]);
        g_Wpk[p * 4096 + pos] = make_uint2(h2u(b0), h2u(b1));
    }
}

// ---------------------------------------------------------------------------
// Kernel 1: projection GEMMs, single-term fp16 (proven R11 version).
// ---------------------------------------------------------------------------
__global__ __launch_bounds__(512) void proj_mma_kernel(
    const float* __restrict__ X,
    const float* __restrict__ bq, const float* __restrict__ bk,
    const float* __restrict__ bv)
{
    extern __shared__ float sm[];
    float* Xs  = sm;                        // [m][c] 128 x SSTR fp32 (67.6 KB)
    uint2* Wpk = (uint2*)(sm + 128 * SSTR); // [16 nt][8 ks][32 lane] uint2 (32 KB)

    const int t    = threadIdx.x;
    const int warp = t >> 5;
    const int lane = t & 31;
    const int M0   = blockIdx.x * 128;
    const int bidx = M0 >> 11;
    const int n0   = M0 & 2047;

    {
        const int r  = t >> 5;
        const int c4 = (t & 31) << 2;
        #pragma unroll
        for (int it = 0; it < 8; ++it) {
            const int row = it * 16 + r;
            float4 xv = *(const float4*)(X + (size_t)(M0 + row) * CDIM + c4);
            *(float4*)(Xs + row * SSTR + c4) = xv;
        }
    }

    const int g      = lane >> 2;
    const int tid    = lane & 3;
    const int mgroup = warp & 7;
    const int nhalf  = warp >> 3;
    const int mbase  = mgroup * 16;

    #pragma unroll 1
    for (int p = 0; p < 3; ++p) {
        const float* bias = (p == 0) ? bq : (p == 1) ? bk : bv;
        float* OutT       = (p == 0) ? g_QT : (p == 1) ? g_KT : g_VT;

        __syncthreads();

        {
            const uint4* src = (const uint4*)&g_Wpk[p * 4096];
            uint4* dst = (uint4*)Wpk;
            #pragma unroll
            for (int i = 0; i < 4; ++i)
                dst[t + i * 512] = src[t + i * 512];
        }
        __syncthreads();

        float acc[8][4];
        #pragma unroll
        for (int nt = 0; nt < 8; ++nt)
            #pragma unroll
            for (int q = 0; q < 4; ++q) acc[nt][q] = 0.0f;

        #pragma unroll
        for (int ks = 0; ks < 8; ++ks) {
            const int c0 = ks * 16 + 2 * tid;
            const float* xr0 = Xs + (mbase + g) * SSTR + c0;
            const float* xr1 = Xs + (mbase + g + 8) * SSTR + c0;
            float2 x00 = *(const float2*)(xr0);
            float2 x02 = *(const float2*)(xr0 + 8);
            float2 x10 = *(const float2*)(xr1);
            float2 x12 = *(const float2*)(xr1 + 8);
            uint32_t a0 = h2u(__floats2half2_rn(x00.x, x00.y));
            uint32_t a1 = h2u(__floats2half2_rn(x10.x, x10.y));
            uint32_t a2 = h2u(__floats2half2_rn(x02.x, x02.y));
            uint32_t a3 = h2u(__floats2half2_rn(x12.x, x12.y));

            #pragma unroll
            for (int nt = 0; nt < 8; ++nt) {
                const int ntg = nhalf * 8 + nt;
                uint2 w = Wpk[(ntg * 8 + ks) * 32 + lane];
                mma_f16(acc[nt][0], acc[nt][1], acc[nt][2], acc[nt][3],
                        a0, a1, a2, a3, w.x, w.y);
            }
        }

        __syncthreads();

        float* T = (float*)Wpk;
        #pragma unroll
        for (int nt = 0; nt < 8; ++nt) {
            const int j0 = nhalf * 64 + nt * 8 + 2 * tid;
            const float b0v = __ldg(bias + j0);
            const float b1v = __ldg(bias + j0 + 1);
            float v0 = acc[nt][0] + b0v;
            float v1 = acc[nt][1] + b1v;
            float v2 = acc[nt][2] + b0v;
            float v3 = acc[nt][3] + b1v;
            v0 = 1.0f / (1.0f + __expf(-v0));
            v1 = 1.0f / (1.0f + __expf(-v1));
            v2 = 1.0f / (1.0f + __expf(-v2));
            v3 = 1.0f / (1.0f + __expf(-v3));
            T[j0 * SSTR + mbase + g]           = v0;
            T[(j0 + 1) * SSTR + mbase + g]     = v1;
            T[j0 * SSTR + mbase + g + 8]       = v2;
            T[(j0 + 1) * SSTR + mbase + g + 8] = v3;
        }
        __syncthreads();

        #pragma unroll
        for (int it = 0; it < 8; ++it) {
            const int idx = t + it * 512;
            const int j   = idx >> 5;
            const int m4  = (idx & 31) << 2;
            float4 v = *(const float4*)(T + j * SSTR + m4);
            *(float4*)(OutT + ((size_t)bidx * CDIM + j) * NSEQ + n0 + m4) = v;
        }
    }
}

// ---------------------------------------------------------------------------
// Kernel 2: per-(b,c) dual-softmax attention. Same phase structure, warp
// ownership, and summation order as the proven R4 kernel, but all operand
// broadcasts are PACKED so one LDS.128 broadcast feeds 4-8 FMAs:
//   qpk  [warp][w*4+gi]      (pooled q, phase A)
//   Qpk  [h>>3][w*8+(h&7)]   (Q rows, phase C)
//   Ppk  [warp][h*4+gi] in A->B, then [warp][g*8+hi] in C->D
// Wavefronts/CTA drop ~9.1K -> ~3.8K; FMA becomes the floor.
// ---------------------------------------------------------------------------
__global__ __launch_bounds__(256) void attn_kernel()
{
    const int bc = blockIdx.x;                      // b*128 + c
    const float* Qp = g_QT + (size_t)bc * NSEQ;
    const float* Kp = g_KT + (size_t)bc * NSEQ;
    const float* Vp = g_VT + (size_t)bc * NSEQ;
    float* Op = g_VT + (size_t)bc * NSEQ;           // overwrite V plane

    __shared__ float Qs[HP * WP];     // [h][w]
    __shared__ float Vs[HP * WP];     // [h][w]
    __shared__ float KTs[WP * 65];    // [w][h], padded
    __shared__ float kTs[WP * 33];    // [w][g], pooled K, padded
    __shared__ float qpk[8 * 128];    // pooled q packed: [g>>2][w*4+(g&3)]
    __shared__ float Qpk[8 * 256];    // Q packed: [h>>3][w*8+(h&7)]
    __shared__ float Kqvs[HG * WP];   // [g][w]
    __shared__ float Ppk[8 * 256];    // probs packed (phase A->B, then C->D)

    const int t    = threadIdx.x;
    const int warp = t >> 5;
    const int lane = t & 31;
    const unsigned FULL = 0xffffffffu;

    // ---- Load; K transposed; Q also packed [w][hi] for phase C ----
    #pragma unroll
    for (int i = 0; i < 2; ++i) {
        int idx = (t + i * 256) * 4;
        float4 qv = *(const float4*)(Qp + idx);
        float4 vv = *(const float4*)(Vp + idx);
        float4 kv = *(const float4*)(Kp + idx);
        *(float4*)(Qs + idx) = qv;
        *(float4*)(Vs + idx) = vv;
        int h = idx >> 5, w = idx & 31;
        KTs[(w + 0) * 65 + h] = kv.x;
        KTs[(w + 1) * 65 + h] = kv.y;
        KTs[(w + 2) * 65 + h] = kv.z;
        KTs[(w + 3) * 65 + h] = kv.w;
        float* qd = Qpk + (h >> 3) * 256 + (h & 7);
        qd[(w + 0) * 8] = qv.x;
        qd[(w + 1) * 8] = qv.y;
        qd[(w + 2) * 8] = qv.z;
        qd[(w + 3) * 8] = qv.w;
    }
    __syncthreads();

    // ---- Pool over h pairs; q written packed ----
    #pragma unroll
    for (int i = 0; i < 4; ++i) {
        int idx = t + i * 256;
        int g = idx >> 5, w = idx & 31;
        qpk[(g >> 2) * 128 + w * 4 + (g & 3)] =
            0.5f * (Qs[(2 * g) * 32 + w] + Qs[(2 * g + 1) * 32 + w]);
        kTs[w * 33 + g] = 0.5f * (KTs[w * 65 + 2 * g] + KTs[w * 65 + 2 * g + 1]);
    }
    __syncthreads();

    const int g0 = warp * 4;
    // ---- Phase A: S1[g][h] = q[g]·K[h]; softmax over h. Warp owns g0..g0+3,
    //      lane covers h = lane, lane+32. q via one float4 broadcast/iter. ----
    {
        float s0[4] = {0, 0, 0, 0}, s1[4] = {0, 0, 0, 0};
        #pragma unroll
        for (int w = 0; w < 32; ++w) {
            float k0 = KTs[w * 65 + lane];
            float k1 = KTs[w * 65 + 32 + lane];
            float4 qv = *(const float4*)(qpk + warp * 128 + w * 4);
            s0[0] = fmaf(qv.x, k0, s0[0]);  s1[0] = fmaf(qv.x, k1, s1[0]);
            s0[1] = fmaf(qv.y, k0, s0[1]);  s1[1] = fmaf(qv.y, k1, s1[1]);
            s0[2] = fmaf(qv.z, k0, s0[2]);  s1[2] = fmaf(qv.z, k1, s1[2]);
            s0[3] = fmaf(qv.w, k0, s0[3]);  s1[3] = fmaf(qv.w, k1, s1[3]);
        }
        float p0[4], p1[4];
        #pragma unroll
        for (int gi = 0; gi < 4; ++gi) {
            float a = s0[gi] * D_SCALE, b = s1[gi] * D_SCALE;
            float m = fmaxf(a, b);
            #pragma unroll
            for (int o = 16; o; o >>= 1) m = fmaxf(m, __shfl_xor_sync(FULL, m, o));
            float e0 = __expf(a - m), e1 = __expf(b - m);
            float sum = e0 + e1;
            #pragma unroll
            for (int o = 16; o; o >>= 1) sum += __shfl_xor_sync(FULL, sum, o);
            float r = __frcp_rn(sum);
            p0[gi] = e0 * r;
            p1[gi] = e1 * r;
        }
        // pack P1: Ppk[warp][h*4+gi]
        *(float4*)(Ppk + warp * 256 + lane * 4)        = make_float4(p0[0], p0[1], p0[2], p0[3]);
        *(float4*)(Ppk + warp * 256 + (lane + 32) * 4) = make_float4(p1[0], p1[1], p1[2], p1[3]);
        __syncwarp();

        // ---- Phase B: Kqv[g0+gi][w] = sum_h P1 V; lane = w. 2 wf per h. ----
        float acc[4] = {0, 0, 0, 0};
        #pragma unroll 8
        for (int h = 0; h < 64; ++h) {
            float4 p = *(const float4*)(Ppk + warp * 256 + h * 4);
            float v = Vs[h * 32 + lane];
            acc[0] = fmaf(p.x, v, acc[0]);
            acc[1] = fmaf(p.y, v, acc[1]);
            acc[2] = fmaf(p.z, v, acc[2]);
            acc[3] = fmaf(p.w, v, acc[3]);
        }
        Kqvs[(g0 + 0) * 32 + lane] = acc[0];
        Kqvs[(g0 + 1) * 32 + lane] = acc[1];
        Kqvs[(g0 + 2) * 32 + lane] = acc[2];
        Kqvs[(g0 + 3) * 32 + lane] = acc[3];
    }
    __syncthreads();

    const int h0 = warp * 8;
    // ---- Phase C: S2[h][g] = Q[h]·kp[g]; softmax over g. Warp owns h0..h0+7,
    //      lane = g. Q via two float4 broadcasts/iter. ----
    {
        float s[8] = {0, 0, 0, 0, 0, 0, 0, 0};
        #pragma unroll
        for (int w = 0; w < 32; ++w) {
            float kt = kTs[w * 33 + lane];
            float4 qa = *(const float4*)(Qpk + warp * 256 + w * 8);
            float4 qb = *(const float4*)(Qpk + warp * 256 + w * 8 + 4);
            s[0] = fmaf(qa.x, kt, s[0]);
            s[1] = fmaf(qa.y, kt, s[1]);
            s[2] = fmaf(qa.z, kt, s[2]);
            s[3] = fmaf(qa.w, kt, s[3]);
            s[4] = fmaf(qb.x, kt, s[4]);
            s[5] = fmaf(qb.y, kt, s[5]);
            s[6] = fmaf(qb.z, kt, s[6]);
            s[7] = fmaf(qb.w, kt, s[7]);
        }
        float p2[8];
        #pragma unroll
        for (int hi = 0; hi < 8; ++hi) {
            float a = s[hi] * D_SCALE;
            float m = a;
            #pragma unroll
            for (int o = 16; o; o >>= 1) m = fmaxf(m, __shfl_xor_sync(FULL, m, o));
            float e = __expf(a - m);
            float sum = e;
            #pragma unroll
            for (int o = 16; o; o >>= 1) sum += __shfl_xor_sync(FULL, sum, o);
            p2[hi] = e * __frcp_rn(sum);
        }
        // pack P2: Ppk[warp][g*8+hi]  (phase B of all warps done: synced above)
        *(float4*)(Ppk + warp * 256 + lane * 8)     = make_float4(p2[0], p2[1], p2[2], p2[3]);
        *(float4*)(Ppk + warp * 256 + lane * 8 + 4) = make_float4(p2[4], p2[5], p2[6], p2[7]);
        __syncwarp();

        // ---- Phase D: out[h0+hi][w] = sum_g P2 Kqv; lane = w. 3 wf per g. ----
        float acc[8] = {0, 0, 0, 0, 0, 0, 0, 0};
        #pragma unroll 8
        for (int g = 0; g < 32; ++g) {
            float4 pa = *(const float4*)(Ppk + warp * 256 + g * 8);
            float4 pb = *(const float4*)(Ppk + warp * 256 + g * 8 + 4);
            float kv = Kqvs[g * 32 + lane];
            acc[0] = fmaf(pa.x, kv, acc[0]);
            acc[1] = fmaf(pa.y, kv, acc[1]);
            acc[2] = fmaf(pa.z, kv, acc[2]);
            acc[3] = fmaf(pa.w, kv, acc[3]);
            acc[4] = fmaf(pb.x, kv, acc[4]);
            acc[5] = fmaf(pb.y, kv, acc[5]);
            acc[6] = fmaf(pb.z, kv, acc[6]);
            acc[7] = fmaf(pb.w, kv, acc[7]);
        }
        #pragma unroll
        for (int hi = 0; hi < 8; ++hi)
            Op[(h0 + hi) * 32 + lane] = acc[hi];
    }
}

// ---------------------------------------------------------------------------
// Kernel 3: [B, C, N] -> [B, N, C] transpose (output epilogue).
// ---------------------------------------------------------------------------
__global__ __launch_bounds__(256) void transpose_kernel(float* __restrict__ out)
{
    __shared__ float tile[32][33];
    const int b  = blockIdx.z;
    const int c0 = blockIdx.y * 32;
    const int n0 = blockIdx.x * 32;
    const int tx = threadIdx.x;
    const int ty = threadIdx.y;

    const float* src = g_VT + (size_t)b * CDIM * NSEQ;
    #pragma unroll
    for (int i = 0; i < 32; i += 8)
        tile[ty + i][tx] = src[(size_t)(c0 + ty + i) * NSEQ + n0 + tx];
    __syncthreads();
    #pragma unroll
    for (int i = 0; i < 32; i += 8)
        out[((size_t)b * NSEQ + n0 + ty + i) * CDIM + c0 + tx] = tile[tx][ty + i];
}

// ---------------------------------------------------------------------------
extern "C" void kernel_launch(void* const* d_in, const int* in_sizes, int n_in,
                              void* d_out, int out_size)
{
    (void)in_sizes; (void)n_in; (void)out_size;
    const float* X  = (const float*)d_in[0];
    const float* Wq = (const float*)d_in[1];
    const float* bq = (const float*)d_in[2];
    const float* Wk = (const float*)d_in[3];
    const float* bk = (const float*)d_in[4];
    const float* Wv = (const float*)d_in[5];
    const float* bv = (const float*)d_in[6];
    float* out = (float*)d_out;

    const size_t proj_smem = (size_t)2 * 128 * SSTR * sizeof(float);  // 135168 B
    cudaFuncSetAttribute(proj_mma_kernel, cudaFuncAttributeMaxDynamicSharedMemorySize,
                         (int)proj_smem);

    prep_w_kernel<<<dim3(3, 1, 1), 256>>>(Wq, Wk, Wv);
    proj_mma_kernel<<<dim3(1024, 1, 1), 512, proj_smem>>>(X, bq, bk, bv);
    attn_kernel<<<dim3(BATCH * CDIM, 1, 1), 256>>>();
    transpose_kernel<<<dim3(NSEQ / 32, CDIM / 32, BATCH), dim3(32, 8, 1)>>>(out);
}

// round 13
// speedup vs baseline: 1.3135x; 1.0171x over previous
#include <cuda_runtime.h>
#include <cuda_fp16.h>
#include <cstdint>

#define BATCH 64
#define NSEQ  2048
#define CDIM  128
#define HP    64
#define WP    32
#define HG    32   // HP / POOL
#define D_SCALE 0.08838834764831845f  // 1/sqrt(128)

// Scratch: Q,K,V in [B, C, N] (spatial-major) layout. V plane is overwritten
// with the attention output by attn_kernel (each CTA exclusively owns its plane,
// and proj writes it fully on every graph replay -> deterministic).
__device__ float g_QT[(size_t)BATCH * CDIM * NSEQ];
__device__ float g_KT[(size_t)BATCH * CDIM * NSEQ];
__device__ float g_VT[(size_t)BATCH * CDIM * NSEQ];

// Precomputed W fragments (fp16, 2-ks packed):
// [p][(nt*4+kp)*32+lane] -> uint4 (b0@ks=2kp, b1@ks=2kp, b0@ks=2kp+1, b1@ks=2kp+1)
__device__ uint4 g_Wpk[3 * 2048];

#define SSTR 132   // proj epilogue transpose-buffer row stride (floats)

__device__ __forceinline__ uint32_t h2u(__half2 h) {
    return *reinterpret_cast<uint32_t*>(&h);
}

__device__ __forceinline__ void mma_f16(float& d0, float& d1, float& d2, float& d3,
                                        uint32_t a0, uint32_t a1, uint32_t a2, uint32_t a3,
                                        uint32_t b0, uint32_t b1) {
    asm volatile(
        "mma.sync.aligned.m16n8k16.row.col.f32.f16.f16.f32 "
        "{%0,%1,%2,%3}, {%4,%5,%6,%7}, {%8,%9}, {%0,%1,%2,%3};"
        : "+f"(d0), "+f"(d1), "+f"(d2), "+f"(d3)
        : "r"(a0), "r"(a1), "r"(a2), "r"(a3), "r"(b0), "r"(b1));
}

// ---------------------------------------------------------------------------
// Kernel 0: convert W matrices into 2-ks-packed fp16 MMA fragments, once.
// lane = gj*4 + s, j = nt*8 + gj; for kp: ks0=2kp, ks1=2kp+1,
// c0 = ks*16 + 2s:  x=h2(W[j][c0@ks0], W[j][c0+1]), y=h2(W[j][c0+8], W[j][c0+9]),
//                   z,w = same for ks1.
// ---------------------------------------------------------------------------
__global__ __launch_bounds__(256) void prep_w_kernel(
    const float* __restrict__ Wq, const float* __restrict__ Wk,
    const float* __restrict__ Wv)
{
    const int p = blockIdx.x;
    const float* W = (p == 0) ? Wq : (p == 1) ? Wk : Wv;
    const int t = threadIdx.x;
    #pragma unroll
    for (int i = 0; i < 8; ++i) {
        const int pos  = t + i * 256;        // 0..2047
        const int lane = pos & 31;
        const int kp   = (pos >> 5) & 3;
        const int nt   = pos >> 7;
        const int gj   = lane >> 2;
        const int s    = lane & 3;
        const int j    = nt * 8 + gj;
        const int ca   = (2 * kp) * 16 + 2 * s;
        const int cb   = ca + 16;
        __half2 x = __floats2half2_rn(W[j * CDIM + ca],     W[j * CDIM + ca + 1]);
        __half2 y = __floats2half2_rn(W[j * CDIM + ca + 8], W[j * CDIM + ca + 9]);
        __half2 z = __floats2half2_rn(W[j * CDIM + cb],     W[j * CDIM + cb + 1]);
        __half2 w = __floats2half2_rn(W[j * CDIM + cb + 8], W[j * CDIM + cb + 9]);
        g_Wpk[p * 2048 + pos] = make_uint4(h2u(x), h2u(y), h2u(z), h2u(w));
    }
}

// ---------------------------------------------------------------------------
// Kernel 1: projection GEMMs, single-term fp16, BOTH operands fragment-packed.
// A packed once at staging: Apk[(mt*8+ks)*32 + lane] -> uint4 (a0,a1,a2,a3).
// Mainloop per 2 ks: 2 LDS.128 (A) + 8 LDS.128 (W) + 16 MMA.
// MMA issue order per acc identical to R12 -> bit-identical results.
// 512 threads = 16 warps: warp = (mgroup 0..7) x (nhalf 0..1).
// ---------------------------------------------------------------------------
__global__ __launch_bounds__(512) void proj_mma_kernel(
    const float* __restrict__ X,
    const float* __restrict__ bq, const float* __restrict__ bk,
    const float* __restrict__ bv)
{
    extern __shared__ uint4 smq[];
    uint4* Apk = smq;               // [8 mt][8 ks][32 lane]  2048 uint4 (32 KB)
    uint4* Wpk = smq + 2048;        // [16 nt][4 kp][32 lane] 2048 uint4 (32 KB)
    float* T   = (float*)(smq + 4096);  // [128 j][SSTR] transpose buf (67.6 KB)

    const int t    = threadIdx.x;
    const int warp = t >> 5;
    const int lane = t & 31;
    const int M0   = blockIdx.x * 128;
    const int bidx = M0 >> 11;
    const int n0   = M0 & 2047;

    const int g      = lane >> 2;
    const int tid    = lane & 3;
    const int mgroup = warp & 7;
    const int nhalf  = warp >> 3;
    const int mbase  = mgroup * 16;

    // ---- Stage A: pack X into fp16 MMA fragments (once, reused for 3 p's) ----
    #pragma unroll
    for (int i = 0; i < 4; ++i) {
        const int pos = t + i * 512;          // 0..2047
        const int ln  = pos & 31;
        const int ks  = (pos >> 5) & 7;
        const int mt  = pos >> 8;
        const int gg  = ln >> 2;
        const int ss  = ln & 3;
        const int r0  = M0 + mt * 16 + gg;
        const int c0  = ks * 16 + 2 * ss;
        float2 x00 = *(const float2*)(X + (size_t)r0 * CDIM + c0);
        float2 x10 = *(const float2*)(X + (size_t)(r0 + 8) * CDIM + c0);
        float2 x02 = *(const float2*)(X + (size_t)r0 * CDIM + c0 + 8);
        float2 x12 = *(const float2*)(X + (size_t)(r0 + 8) * CDIM + c0 + 8);
        Apk[pos] = make_uint4(h2u(__floats2half2_rn(x00.x, x00.y)),
                              h2u(__floats2half2_rn(x10.x, x10.y)),
                              h2u(__floats2half2_rn(x02.x, x02.y)),
                              h2u(__floats2half2_rn(x12.x, x12.y)));
    }

    #pragma unroll 1
    for (int p = 0; p < 3; ++p) {
        const float* bias = (p == 0) ? bq : (p == 1) ? bk : bv;
        float* OutT       = (p == 0) ? g_QT : (p == 1) ? g_KT : g_VT;

        // ---- Stage W fragments: straight copy (2048 uint4) ----
        // (p==0: also covers A-staging visibility; p>0: prev stores done below)
        #pragma unroll
        for (int i = 0; i < 4; ++i)
            Wpk[t + i * 512] = g_Wpk[p * 2048 + t + i * 512];
        __syncthreads();

        // ---- MMA mainloop: warp owns 16 m-rows x 64 j-cols (8 nt) ----
        float acc[8][4];
        #pragma unroll
        for (int nt = 0; nt < 8; ++nt)
            #pragma unroll
            for (int q = 0; q < 4; ++q) acc[nt][q] = 0.0f;

        #pragma unroll
        for (int kp = 0; kp < 4; ++kp) {
            uint4 Aa = Apk[(mgroup * 8 + 2 * kp) * 32 + lane];
            uint4 Ab = Apk[(mgroup * 8 + 2 * kp + 1) * 32 + lane];
            #pragma unroll
            for (int nt = 0; nt < 8; ++nt) {
                const int ntg = nhalf * 8 + nt;
                uint4 w = Wpk[(ntg * 4 + kp) * 32 + lane];
                mma_f16(acc[nt][0], acc[nt][1], acc[nt][2], acc[nt][3],
                        Aa.x, Aa.y, Aa.z, Aa.w, w.x, w.y);
                mma_f16(acc[nt][0], acc[nt][1], acc[nt][2], acc[nt][3],
                        Ab.x, Ab.y, Ab.z, Ab.w, w.z, w.w);
            }
        }

        // ---- Epilogue: bias + sigmoid, transpose to [j][m] via T ----
        #pragma unroll
        for (int nt = 0; nt < 8; ++nt) {
            const int j0 = nhalf * 64 + nt * 8 + 2 * tid;
            const float b0v = __ldg(bias + j0);
            const float b1v = __ldg(bias + j0 + 1);
            float v0 = acc[nt][0] + b0v;
            float v1 = acc[nt][1] + b1v;
            float v2 = acc[nt][2] + b0v;
            float v3 = acc[nt][3] + b1v;
            v0 = 1.0f / (1.0f + __expf(-v0));
            v1 = 1.0f / (1.0f + __expf(-v1));
            v2 = 1.0f / (1.0f + __expf(-v2));
            v3 = 1.0f / (1.0f + __expf(-v3));
            T[j0 * SSTR + mbase + g]           = v0;
            T[(j0 + 1) * SSTR + mbase + g]     = v1;
            T[j0 * SSTR + mbase + g + 8]       = v2;
            T[(j0 + 1) * SSTR + mbase + g + 8] = v3;
        }
        __syncthreads();

        // ---- Coalesced float4 store: OutT[bidx][j][n0 + m] ----
        #pragma unroll
        for (int it = 0; it < 8; ++it) {
            const int idx = t + it * 512;
            const int j   = idx >> 5;
            const int m4  = (idx & 31) << 2;
            float4 v = *(const float4*)(T + j * SSTR + m4);
            *(float4*)(OutT + ((size_t)bidx * CDIM + j) * NSEQ + n0 + m4) = v;
        }
        __syncthreads();   // stores read T; next p overwrites Wpk (disjoint) + T
    }
}

// ---------------------------------------------------------------------------
// Kernel 2: per-(b,c) dual-softmax attention (proven R12 packed version).
// ---------------------------------------------------------------------------
__global__ __launch_bounds__(256) void attn_kernel()
{
    const int bc = blockIdx.x;                      // b*128 + c
    const float* Qp = g_QT + (size_t)bc * NSEQ;
    const float* Kp = g_KT + (size_t)bc * NSEQ;
    const float* Vp = g_VT + (size_t)bc * NSEQ;
    float* Op = g_VT + (size_t)bc * NSEQ;           // overwrite V plane

    __shared__ float Qs[HP * WP];     // [h][w]
    __shared__ float Vs[HP * WP];     // [h][w]
    __shared__ float KTs[WP * 65];    // [w][h], padded
    __shared__ float kTs[WP * 33];    // [w][g], pooled K, padded
    __shared__ float qpk[8 * 128];    // pooled q packed: [g>>2][w*4+(g&3)]
    __shared__ float Qpk[8 * 256];    // Q packed: [h>>3][w*8+(h&7)]
    __shared__ float Kqvs[HG * WP];   // [g][w]
    __shared__ float Ppk[8 * 256];    // probs packed (phase A->B, then C->D)

    const int t    = threadIdx.x;
    const int warp = t >> 5;
    const int lane = t & 31;
    const unsigned FULL = 0xffffffffu;

    #pragma unroll
    for (int i = 0; i < 2; ++i) {
        int idx = (t + i * 256) * 4;
        float4 qv = *(const float4*)(Qp + idx);
        float4 vv = *(const float4*)(Vp + idx);
        float4 kv = *(const float4*)(Kp + idx);
        *(float4*)(Qs + idx) = qv;
        *(float4*)(Vs + idx) = vv;
        int h = idx >> 5, w = idx & 31;
        KTs[(w + 0) * 65 + h] = kv.x;
        KTs[(w + 1) * 65 + h] = kv.y;
        KTs[(w + 2) * 65 + h] = kv.z;
        KTs[(w + 3) * 65 + h] = kv.w;
        float* qd = Qpk + (h >> 3) * 256 + (h & 7);
        qd[(w + 0) * 8] = qv.x;
        qd[(w + 1) * 8] = qv.y;
        qd[(w + 2) * 8] = qv.z;
        qd[(w + 3) * 8] = qv.w;
    }
    __syncthreads();

    #pragma unroll
    for (int i = 0; i < 4; ++i) {
        int idx = t + i * 256;
        int g = idx >> 5, w = idx & 31;
        qpk[(g >> 2) * 128 + w * 4 + (g & 3)] =
            0.5f * (Qs[(2 * g) * 32 + w] + Qs[(2 * g + 1) * 32 + w]);
        kTs[w * 33 + g] = 0.5f * (KTs[w * 65 + 2 * g] + KTs[w * 65 + 2 * g + 1]);
    }
    __syncthreads();

    const int g0 = warp * 4;
    {
        float s0[4] = {0, 0, 0, 0}, s1[4] = {0, 0, 0, 0};
        #pragma unroll
        for (int w = 0; w < 32; ++w) {
            float k0 = KTs[w * 65 + lane];
            float k1 = KTs[w * 65 + 32 + lane];
            float4 qv = *(const float4*)(qpk + warp * 128 + w * 4);
            s0[0] = fmaf(qv.x, k0, s0[0]);  s1[0] = fmaf(qv.x, k1, s1[0]);
            s0[1] = fmaf(qv.y, k0, s0[1]);  s1[1] = fmaf(qv.y, k1, s1[1]);
            s0[2] = fmaf(qv.z, k0, s0[2]);  s1[2] = fmaf(qv.z, k1, s1[2]);
            s0[3] = fmaf(qv.w, k0, s0[3]);  s1[3] = fmaf(qv.w, k1, s1[3]);
        }
        float p0[4], p1[4];
        #pragma unroll
        for (int gi = 0; gi < 4; ++gi) {
            float a = s0[gi] * D_SCALE, b = s1[gi] * D_SCALE;
            float m = fmaxf(a, b);
            #pragma unroll
            for (int o = 16; o; o >>= 1) m = fmaxf(m, __shfl_xor_sync(FULL, m, o));
            float e0 = __expf(a - m), e1 = __expf(b - m);
            float sum = e0 + e1;
            #pragma unroll
            for (int o = 16; o; o >>= 1) sum += __shfl_xor_sync(FULL, sum, o);
            float r = __frcp_rn(sum);
            p0[gi] = e0 * r;
            p1[gi] = e1 * r;
        }
        *(float4*)(Ppk + warp * 256 + lane * 4)        = make_float4(p0[0], p0[1], p0[2], p0[3]);
        *(float4*)(Ppk + warp * 256 + (lane + 32) * 4) = make_float4(p1[0], p1[1], p1[2], p1[3]);
        __syncwarp();

        float acc[4] = {0, 0, 0, 0};
        #pragma unroll 8
        for (int h = 0; h < 64; ++h) {
            float4 p = *(const float4*)(Ppk + warp * 256 + h * 4);
            float v = Vs[h * 32 + lane];
            acc[0] = fmaf(p.x, v, acc[0]);
            acc[1] = fmaf(p.y, v, acc[1]);
            acc[2] = fmaf(p.z, v, acc[2]);
            acc[3] = fmaf(p.w, v, acc[3]);
        }
        Kqvs[(g0 + 0) * 32 + lane] = acc[0];
        Kqvs[(g0 + 1) * 32 + lane] = acc[1];
        Kqvs[(g0 + 2) * 32 + lane] = acc[2];
        Kqvs[(g0 + 3) * 32 + lane] = acc[3];
    }
    __syncthreads();

    const int h0 = warp * 8;
    {
        float s[8] = {0, 0, 0, 0, 0, 0, 0, 0};
        #pragma unroll
        for (int w = 0; w < 32; ++w) {
            float kt = kTs[w * 33 + lane];
            float4 qa = *(const float4*)(Qpk + warp * 256 + w * 8);
            float4 qb = *(const float4*)(Qpk + warp * 256 + w * 8 + 4);
            s[0] = fmaf(qa.x, kt, s[0]);
            s[1] = fmaf(qa.y, kt, s[1]);
            s[2] = fmaf(qa.z, kt, s[2]);
            s[3] = fmaf(qa.w, kt, s[3]);
            s[4] = fmaf(qb.x, kt, s[4]);
            s[5] = fmaf(qb.y, kt, s[5]);
            s[6] = fmaf(qb.z, kt, s[6]);
            s[7] = fmaf(qb.w, kt, s[7]);
        }
        float p2[8];
        #pragma unroll
        for (int hi = 0; hi < 8; ++hi) {
            float a = s[hi] * D_SCALE;
            float m = a;
            #pragma unroll
            for (int o = 16; o; o >>= 1) m = fmaxf(m, __shfl_xor_sync(FULL, m, o));
            float e = __expf(a - m);
            float sum = e;
            #pragma unroll
            for (int o = 16; o; o >>= 1) sum += __shfl_xor_sync(FULL, sum, o);
            p2[hi] = e * __frcp_rn(sum);
        }
        *(float4*)(Ppk + warp * 256 + lane * 8)     = make_float4(p2[0], p2[1], p2[2], p2[3]);
        *(float4*)(Ppk + warp * 256 + lane * 8 + 4) = make_float4(p2[4], p2[5], p2[6], p2[7]);
        __syncwarp();

        float acc[8] = {0, 0, 0, 0, 0, 0, 0, 0};
        #pragma unroll 8
        for (int g = 0; g < 32; ++g) {
            float4 pa = *(const float4*)(Ppk + warp * 256 + g * 8);
            float4 pb = *(const float4*)(Ppk + warp * 256 + g * 8 + 4);
            float kv = Kqvs[g * 32 + lane];
            acc[0] = fmaf(pa.x, kv, acc[0]);
            acc[1] = fmaf(pa.y, kv, acc[1]);
            acc[2] = fmaf(pa.z, kv, acc[2]);
            acc[3] = fmaf(pa.w, kv, acc[3]);
            acc[4] = fmaf(pb.x, kv, acc[4]);
            acc[5] = fmaf(pb.y, kv, acc[5]);
            acc[6] = fmaf(pb.z, kv, acc[6]);
            acc[7] = fmaf(pb.w, kv, acc[7]);
        }
        #pragma unroll
        for (int hi = 0; hi < 8; ++hi)
            Op[(h0 + hi) * 32 + lane] = acc[hi];
    }
}

// ---------------------------------------------------------------------------
// Kernel 3: [B, C, N] -> [B, N, C] transpose (output epilogue).
// ---------------------------------------------------------------------------
__global__ __launch_bounds__(256) void transpose_kernel(float* __restrict__ out)
{
    __shared__ float tile[32][33];
    const int b  = blockIdx.z;
    const int c0 = blockIdx.y * 32;
    const int n0 = blockIdx.x * 32;
    const int tx = threadIdx.x;
    const int ty = threadIdx.y;

    const float* src = g_VT + (size_t)b * CDIM * NSEQ;
    #pragma unroll
    for (int i = 0; i < 32; i += 8)
        tile[ty + i][tx] = src[(size_t)(c0 + ty + i) * NSEQ + n0 + tx];
    __syncthreads();
    #pragma unroll
    for (int i = 0; i < 32; i += 8)
        out[((size_t)b * NSEQ + n0 + ty + i) * CDIM + c0 + tx] = tile[tx][ty + i];
}

// ---------------------------------------------------------------------------
extern "C" void kernel_launch(void* const* d_in, const int* in_sizes, int n_in,
                              void* d_out, int out_size)
{
    (void)in_sizes; (void)n_in; (void)out_size;
    const float* X  = (const float*)d_in[0];
    const float* Wq = (const float*)d_in[1];
    const float* bq = (const float*)d_in[2];
    const float* Wk = (const float*)d_in[3];
    const float* bk = (const float*)d_in[4];
    const float* Wv = (const float*)d_in[5];
    const float* bv = (const float*)d_in[6];
    float* out = (float*)d_out;

    // Apk (32KB) + Wpk (32KB) + T (128*SSTR*4 = 67584B) = 133120 B
    const size_t proj_smem = 4096 * sizeof(uint4) + (size_t)128 * SSTR * sizeof(float);
    cudaFuncSetAttribute(proj_mma_kernel, cudaFuncAttributeMaxDynamicSharedMemorySize,
                         (int)proj_smem);

    prep_w_kernel<<<dim3(3, 1, 1), 256>>>(Wq, Wk, Wv);
    proj_mma_kernel<<<dim3(1024, 1, 1), 512, proj_smem>>>(X, bq, bk, bv);
    attn_kernel<<<dim3(BATCH * CDIM, 1, 1), 256>>>();
    transpose_kernel<<<dim3(NSEQ / 32, CDIM / 32, BATCH), dim3(32, 8, 1)>>>(out);
}